// round 2
// baseline (speedup 1.0000x reference)
#include <cuda_runtime.h>
#include <cuda_bf16.h>
#include <cstdint>
#include <cstddef>

#define NB 1024
#define NM 14
// L = NM + 2 = 16 layers total

// Ping-pong inflow buffers (device scratch; no allocations allowed).
// Self-resetting protocol:
//   k_layer0 zeroes both buffers at the start of every call.
//   k_mid(l) reads g_inflow[l&1][b], zeroes that slot, accumulates into g_inflow[(l&1)^1].
// => state at the start of every kernel_launch call is re-established.
__device__ float g_inflow[2][NB];

__device__ __forceinline__ float sqrt_approx(float x) {
    float y;
    asm("sqrt.approx.f32 %0, %1;" : "=f"(y) : "f"(x));
    return y;
}
__device__ __forceinline__ void l2pf(const void* p) {
    asm volatile("prefetch.global.L2 [%0];" :: "l"(p));
}

// ---------------------------------------------------------------------------
// Layer 0: one head bucket, 1024 sequential spigots -> warp 0 of block 0.
// Other threads prefetch mid-layer-0 S/theta (12.6 MB) into L2 and zero the
// inflow ping-pong buffers.
// q0[i] goes to g_inflow[0][i]; out[0] = H0 - cum + p_layer.
// ---------------------------------------------------------------------------
__global__ void __launch_bounds__(256, 1)
k_layer0(const float* __restrict__ H0p, const float* __restrict__ S0,
         const float* __restrict__ theta0, const float* __restrict__ precip,
         float* __restrict__ out,
         const float* __restrict__ S_mid, const float* __restrict__ theta_mid)
{
    const int tid  = threadIdx.x;
    const long gtid = (long)blockIdx.x * 256 + tid;   // 0..32767

    // Prefetch mid layer 0 into L2: S = 8 MB (65536 x 128B), theta = 4 MB (32768 x 128B)
    {
        const char* ps = (const char*)S_mid;
        l2pf(ps + gtid * 128);
        l2pf(ps + (gtid + 32768) * 128);
        const char* pt = (const char*)theta_mid;
        l2pf(pt + gtid * 128);
    }

    if (blockIdx.x != 0) return;

    for (int i = tid; i < NB; i += 256) {
        g_inflow[0][i] = 0.0f;
        g_inflow[1][i] = 0.0f;
    }
    __syncthreads();
    if (tid >= 32) return;

    const int lane = tid;
    const float p_layer = precip[0] * (1.0f / 16.0f);
    const float H0 = H0p[0];
    const float SQ2G = sqrtf(19.6f);
    const float2* __restrict__ S2 = (const float2*)S0;

    // spigot 0 uses H_eff = H0 + inflow; all later spigots use H0 - 0.5*cum
    float cum;
    {
        float bh0 = S0[0], a0 = S0[1], t0 = theta0[0];
        float h0 = fmaxf((H0 + p_layer) - bh0, 0.0f);
        float q0 = t0 * sqrt_approx(19.6f * h0) * a0;
        cum = q0;
        if (lane == 0 && q0 != 0.0f) g_inflow[0][0] = q0;
    }
    float H_eff = fmaf(-0.5f, cum, H0);

    for (int w = 0; w < 32; ++w) {
        float2 s = S2[w * 32 + lane];
        float th = theta0[w * 32 + lane];
        float bh = s.x;
        float c  = th * s.y * SQ2G;
        unsigned rem = (w == 0) ? 0xFFFFFFFEu : 0xFFFFFFFFu;
        while (true) {
            unsigned fire = __ballot_sync(0xFFFFFFFFu, H_eff > bh) & rem;
            if (!fire) break;
            int f = __ffs(fire) - 1;             // lowest firing spigot
            float bhf = __shfl_sync(0xFFFFFFFFu, bh, f);
            float cf  = __shfl_sync(0xFFFFFFFFu, c,  f);
            float q = cf * sqrt_approx(H_eff - bhf);
            cum += q;
            H_eff = fmaf(-0.5f, cum, H0);
            if (lane == f) g_inflow[0][w * 32 + f] = q;
            rem &= (0xFFFFFFFEu << f);           // only lanes strictly above f remain
        }
    }
    if (lane == 0) out[0] = (H0 - cum) + p_layer;
}

// ---------------------------------------------------------------------------
// Mid layer l: one warp per bucket (1024 warps across 256 blocks x 128 thr).
// Dry spigots skipped via ballot (exact). Firing spigots atomicAdd into the
// next layer's inflow buffer (inflow[j] = sum_b q[b][j]).
// ---------------------------------------------------------------------------
__global__ void __launch_bounds__(128, 1)
k_mid(int l, const float* __restrict__ H_mid, const float* __restrict__ S_mid,
      const float* __restrict__ theta_mid, const float* __restrict__ precip,
      float* __restrict__ out)
{
    const int lane = threadIdx.x & 31;
    const int b    = (blockIdx.x * 128 + threadIdx.x) >> 5;   // 0..1023
    const int cur  = l & 1;
    float* __restrict__ nxt = g_inflow[cur ^ 1];

    const float p_bucket = precip[0] * (1.0f / (16.0f * 1024.0f));
    const size_t rowoff = ((size_t)l * NB + (size_t)b);
    const float2* __restrict__ S2 = (const float2*)S_mid + rowoff * NB;
    const float*  __restrict__ T  = theta_mid + rowoff * NB;

    // Prefetch next layer's rows for this bucket into L2 (8KB + 4KB per warp)
    if (l + 1 < NM) {
        const char* ps = (const char*)((const float2*)S_mid + (rowoff + NB) * NB);
        const char* pt = (const char*)(theta_mid + (rowoff + NB) * NB);
        l2pf(ps + (size_t)lane * 128);
        l2pf(ps + (size_t)(lane + 32) * 128);
        l2pf(pt + (size_t)lane * 128);
    }

    // Read my inflow, then zero the slot (it becomes layer l+1's accumulator)
    float inf0 = 0.0f;
    if (lane == 0) {
        inf0 = g_inflow[cur][b];
        g_inflow[cur][b] = 0.0f;
    }
    const float inflow = __shfl_sync(0xFFFFFFFFu, inf0, 0) + p_bucket;

    const float H0 = H_mid[(size_t)l * NB + b];
    const float SQ2G = sqrtf(19.6f);

    // 4-deep register FIFO of 32-spigot windows to hide load latency
    float2 sbuf[4]; float tbuf[4];
    #pragma unroll
    for (int d = 0; d < 4; ++d) {
        sbuf[d] = S2[d * 32 + lane];
        tbuf[d] = T[d * 32 + lane];
    }

    float cum;
    {
        float bh0 = ((const float*)S2)[0];
        float a0  = ((const float*)S2)[1];
        float t0  = T[0];
        float h0 = fmaxf((H0 + inflow) - bh0, 0.0f);
        float q0 = t0 * sqrt_approx(19.6f * h0) * a0;
        cum = q0;
        if (lane == 0 && q0 != 0.0f) atomicAdd(&nxt[0], q0);
    }
    float H_eff = fmaf(-0.5f, cum, H0);

    for (int g = 0; g < 8; ++g) {
        #pragma unroll
        for (int d = 0; d < 4; ++d) {
            const int w = g * 4 + d;
            float2 s = sbuf[d];
            float th = tbuf[d];
            if (g < 7) {
                sbuf[d] = S2[(w + 4) * 32 + lane];
                tbuf[d] = T[(w + 4) * 32 + lane];
            }
            float bh = s.x;
            float c  = th * s.y * SQ2G;
            unsigned rem = (w == 0) ? 0xFFFFFFFEu : 0xFFFFFFFFu;
            while (true) {
                unsigned fire = __ballot_sync(0xFFFFFFFFu, H_eff > bh) & rem;
                if (!fire) break;
                int f = __ffs(fire) - 1;
                float bhf = __shfl_sync(0xFFFFFFFFu, bh, f);
                float cf  = __shfl_sync(0xFFFFFFFFu, c,  f);
                float q = cf * sqrt_approx(H_eff - bhf);
                cum += q;
                H_eff = fmaf(-0.5f, cum, H0);
                if (lane == f) atomicAdd(&nxt[w * 32 + f], q);
                rem &= (0xFFFFFFFEu << f);
            }
        }
    }
    if (lane == 0) out[1 + l * NB + b] = (H0 - cum) + inflow;
}

// ---------------------------------------------------------------------------
// Last layer: 1024 buckets, one outlet spigot each (fully parallel).
// Final inflows are in g_inflow[0] (layer 13 accumulates into (13&1)^1 == 0).
// ---------------------------------------------------------------------------
__global__ void __launch_bounds__(256)
k_last(const float* __restrict__ H_last, const float* __restrict__ S_last,
       const float* __restrict__ theta_last, const float* __restrict__ precip,
       float* __restrict__ out)
{
    int j = blockIdx.x * 256 + threadIdx.x;
    if (j >= NB) return;
    const float p_bucket = precip[0] * (1.0f / (16.0f * 1024.0f));
    float inflow = g_inflow[0][j] + p_bucket;
    float H0 = H_last[j];
    float bh = S_last[2 * j + 0];
    float a  = S_last[2 * j + 1];
    float h  = fmaxf((H0 + inflow) - bh, 0.0f);
    float q  = theta_last[j] * sqrt_approx(19.6f * h) * a;
    out[1 + NM * NB + j]      = (H0 - q) + inflow;   // H_last_new
    out[1 + NM * NB + NB + j] = q;                   // q_last
}

// ---------------------------------------------------------------------------
extern "C" void kernel_launch(void* const* d_in, const int* in_sizes, int n_in,
                              void* d_out, int out_size)
{
    const float* H0         = (const float*)d_in[0];
    const float* H_mid      = (const float*)d_in[1];
    const float* H_last     = (const float*)d_in[2];
    const float* S0         = (const float*)d_in[3];
    const float* S_mid      = (const float*)d_in[4];
    const float* S_last     = (const float*)d_in[5];
    const float* theta0     = (const float*)d_in[6];
    const float* theta_mid  = (const float*)d_in[7];
    const float* theta_last = (const float*)d_in[8];
    const float* precip     = (const float*)d_in[9];
    float* out = (float*)d_out;

    k_layer0<<<128, 256>>>(H0, S0, theta0, precip, out, S_mid, theta_mid);
    for (int l = 0; l < NM; ++l)
        k_mid<<<256, 128>>>(l, H_mid, S_mid, theta_mid, precip, out);
    k_last<<<4, 256>>>(H_last, S_last, theta_last, precip, out);
}

// round 3
// speedup vs baseline: 1.2204x; 1.2204x over previous
#include <cuda_runtime.h>
#include <cuda_bf16.h>
#include <cstdint>
#include <cstddef>

#define NB 1024
#define NM 14
// L = NM + 2 = 16 layers

// Ping-pong inflow buffers. Self-resetting protocol per kernel_launch call:
//   k_layer0 zeroes both; k_mid(l) reads g_inflow[l&1][b], zeroes that slot,
//   accumulates into g_inflow[(l&1)^1]. State is re-established every call.
__device__ float g_inflow[2][NB];

__device__ __forceinline__ float sqrt_approx(float x) {
    float y;
    asm("sqrt.approx.f32 %0, %1;" : "=f"(y) : "f"(x));
    return y;
}
__device__ __forceinline__ void l2pf(const void* p) {
    asm volatile("prefetch.global.L2 [%0];" :: "l"(p));
}

// ---------------------------------------------------------------------------
// Shared-memory bucket solver core.
// Inputs staged in shared: sh_bh[1024] (spigot heights), sh_c[1024]
// (c = theta*area*sqrt(2g)). Warp 0 runs the exact sequential recurrence:
//   spigot fires iff H_eff > bh (dry spigots leave H_eff bit-identical, so
//   they are skipped without changing results). Firing events are recorded
//   in sh_fidx/sh_fq; returns cum (warp-uniform). minbh_lane = min bh of
//   window 'lane' enables whole-window skipping (H_eff is monotone down).
// ---------------------------------------------------------------------------
struct BucketSmem {
    float bh[NB];
    float c[NB];
    float red[128];
    int   fidx[NB];
    float fq[NB];
};

__device__ __forceinline__ int run_chain(BucketSmem& sm, int lane, float H0,
                                         float inflow, float minbh_lane,
                                         float& cum_out)
{
    const unsigned FULL = 0xFFFFFFFFu;
    int cnt = 0;

    // spigot 0: uses H_eff = H0 + inflow
    float h0 = fmaxf((H0 + inflow) - sm.bh[0], 0.0f);
    float q0 = sm.c[0] * sqrt_approx(h0);
    float cum = q0;
    if (q0 != 0.0f) { sm.fidx[0] = 0; sm.fq[0] = q0; cnt = 1; }
    float H_eff = fmaf(-0.5f, cum, H0);

    unsigned wrem = FULL;   // windows not yet drained
    while (true) {
        unsigned wf = __ballot_sync(FULL, H_eff > minbh_lane) & wrem;
        if (!wf) break;
        int w = __ffs(wf) - 1;                 // first window with a firing spigot
        wrem &= (0xFFFFFFFEu << w);            // windows <= w are done forever
        float bh_l = sm.bh[w * 32 + lane];
        float c_l  = sm.c [w * 32 + lane];
        unsigned rem = (w == 0) ? 0xFFFFFFFEu : FULL;   // spigot 0 already done
        while (true) {
            float h = H_eff - bh_l;
            float q = c_l * sqrt_approx(h);    // speculative; only firing lane used
            unsigned fire = __ballot_sync(FULL, h > 0.0f) & rem;
            if (!fire) break;
            int f = __ffs(fire) - 1;           // lowest firing spigot index
            float qf = __shfl_sync(FULL, q, f);
            cum += qf;
            H_eff = fmaf(-0.5f, cum, H0);
            sm.fidx[cnt] = w * 32 + f;         // all lanes: same addr, same value
            sm.fq[cnt]   = qf;
            ++cnt;
            rem &= (0xFFFFFFFEu << f);
        }
    }
    cum_out = cum;
    return cnt;
}

// Cooperative staging: load S row (interleaved bh,area pairs) and theta row,
// compute c, fill sh_bh/sh_c, and per-window min reduction into sh_red.
__device__ __forceinline__ void stage_bucket(BucketSmem& sm, int tid,
                                             const float* __restrict__ Srow,
                                             const float* __restrict__ Trow)
{
    const float SQ2G = 4.42718872424f;   // sqrt(19.6)
    const float4* S4 = (const float4*)Srow;   // 512 float4 (pairs 2i,2i+1)
    const float4* T4 = (const float4*)Trow;   // 256 float4
    #pragma unroll
    for (int k = 0; k < 4; ++k) {
        int i = tid + k * 128;
        float4 v = S4[i];
        sm.bh[2 * i]     = v.x;  sm.c[2 * i]     = v.y;   // c holds area for now
        sm.bh[2 * i + 1] = v.z;  sm.c[2 * i + 1] = v.w;
    }
    __syncthreads();
    #pragma unroll
    for (int k = 0; k < 2; ++k) {
        int i = tid + k * 128;
        float4 t = T4[i];
        sm.c[4 * i + 0] = t.x * sm.c[4 * i + 0] * SQ2G;
        sm.c[4 * i + 1] = t.y * sm.c[4 * i + 1] * SQ2G;
        sm.c[4 * i + 2] = t.z * sm.c[4 * i + 2] * SQ2G;
        sm.c[4 * i + 3] = t.w * sm.c[4 * i + 3] * SQ2G;
    }
    // per-thread min over 8 bh values
    {
        const float4* B4 = (const float4*)sm.bh;
        float4 a = B4[2 * tid], b = B4[2 * tid + 1];
        float m = fminf(fminf(fminf(a.x, a.y), fminf(a.z, a.w)),
                        fminf(fminf(b.x, b.y), fminf(b.z, b.w)));
        sm.red[tid] = m;
    }
    __syncthreads();
}

// ---------------------------------------------------------------------------
// Layer 0: block 0 solves the head bucket from shared; blocks 1..96 prefetch
// mid-layer-0 S/theta (12.6 MB) into L2. Block 0 also zeroes both inflow
// buffers, then writes q0[i] into g_inflow[0][i].
// ---------------------------------------------------------------------------
__global__ void __launch_bounds__(128)
k_layer0(const float* __restrict__ H0p, const float* __restrict__ S0,
         const float* __restrict__ theta0, const float* __restrict__ precip,
         float* __restrict__ out,
         const float* __restrict__ S_mid, const float* __restrict__ theta_mid)
{
    __shared__ BucketSmem sm;
    const int tid = threadIdx.x;

    if (blockIdx.x != 0) {
        // prefetch mid layer 0: S = 65536 lines, theta = 32768 lines (128B)
        long t = (long)(blockIdx.x - 1) * 128 + tid;   // 0..12287
        #pragma unroll
        for (int k = 0; k < 8; ++k) {
            long line = t + (long)k * 12288;
            if (line < 65536)
                l2pf((const char*)S_mid + line * 128);
            else
                l2pf((const char*)theta_mid + (line - 65536) * 128);
        }
        return;
    }

    // zero both inflow buffers (before chain stores; __syncthreads in stage)
    #pragma unroll
    for (int k = 0; k < 8; ++k) {
        int i = tid + k * 128;
        g_inflow[0][i] = 0.0f;
        g_inflow[1][i] = 0.0f;
    }

    stage_bucket(sm, tid, S0, theta0);

    if (tid < 32) {
        const int lane = tid;
        const float p_layer = precip[0] * (1.0f / 16.0f);
        const float H0 = H0p[0];
        float4 r = ((const float4*)sm.red)[lane];
        float minbh = fminf(fminf(r.x, r.y), fminf(r.z, r.w));
        float cum;
        int cnt = run_chain(sm, lane, H0, p_layer, minbh, cum);
        for (int i = lane; i < cnt; i += 32)
            g_inflow[0][sm.fidx[i]] = sm.fq[i];
        if (lane == 0) out[0] = (H0 - cum) + p_layer;
    }
}

// ---------------------------------------------------------------------------
// Mid layer l: one block per bucket (1024 blocks x 128 threads).
// ---------------------------------------------------------------------------
__global__ void __launch_bounds__(128)
k_mid(int l, const float* __restrict__ H_mid, const float* __restrict__ S_mid,
      const float* __restrict__ theta_mid, const float* __restrict__ precip,
      float* __restrict__ out)
{
    __shared__ BucketSmem sm;
    __shared__ float sh_inflow;
    const int tid = threadIdx.x;
    const int b   = blockIdx.x;
    const int cur = l & 1;
    float* __restrict__ nxt = g_inflow[cur ^ 1];

    const size_t rowoff = (size_t)l * NB + (size_t)b;
    const float* Srow = S_mid + rowoff * NB * 2;
    const float* Trow = theta_mid + rowoff * NB;

    // read my inflow and zero the slot (it becomes layer l+1's accumulator)
    if (tid == 0) {
        sh_inflow = g_inflow[cur][b];
        g_inflow[cur][b] = 0.0f;
    }

    // prefetch next layer's rows for this bucket into L2 (8KB S + 4KB theta)
    if (l + 1 < NM) {
        const char* ps = (const char*)(Srow + (size_t)NB * NB * 2);
        const char* pt = (const char*)(Trow + (size_t)NB * NB);
        if (tid < 64)       l2pf(ps + (size_t)tid * 128);
        else if (tid < 96)  l2pf(pt + (size_t)(tid - 64) * 128);
    }

    stage_bucket(sm, tid, Srow, Trow);   // contains the __syncthreads

    if (tid < 32) {
        const int lane = tid;
        const float p_bucket = precip[0] * (1.0f / (16.0f * 1024.0f));
        const float inflow = sh_inflow + p_bucket;
        const float H0 = H_mid[rowoff];
        float4 r = ((const float4*)sm.red)[lane];
        float minbh = fminf(fminf(r.x, r.y), fminf(r.z, r.w));
        float cum;
        int cnt = run_chain(sm, lane, H0, inflow, minbh, cum);
        for (int i = lane; i < cnt; i += 32)
            atomicAdd(&nxt[sm.fidx[i]], sm.fq[i]);
        if (lane == 0) out[1 + l * NB + b] = (H0 - cum) + inflow;
    }
}

// ---------------------------------------------------------------------------
// Last layer: 1024 buckets, one outlet spigot each (fully parallel).
// Final inflows are in g_inflow[0] (layer 13 writes to (13&1)^1 == 0).
// ---------------------------------------------------------------------------
__global__ void __launch_bounds__(256)
k_last(const float* __restrict__ H_last, const float* __restrict__ S_last,
       const float* __restrict__ theta_last, const float* __restrict__ precip,
       float* __restrict__ out)
{
    int j = blockIdx.x * 256 + threadIdx.x;
    if (j >= NB) return;
    const float p_bucket = precip[0] * (1.0f / (16.0f * 1024.0f));
    float inflow = g_inflow[0][j] + p_bucket;
    float H0 = H_last[j];
    float bh = S_last[2 * j + 0];
    float a  = S_last[2 * j + 1];
    float h  = fmaxf((H0 + inflow) - bh, 0.0f);
    float q  = theta_last[j] * sqrt_approx(19.6f * h) * a;
    out[1 + NM * NB + j]      = (H0 - q) + inflow;   // H_last_new
    out[1 + NM * NB + NB + j] = q;                   // q_last
}

// ---------------------------------------------------------------------------
extern "C" void kernel_launch(void* const* d_in, const int* in_sizes, int n_in,
                              void* d_out, int out_size)
{
    const float* H0         = (const float*)d_in[0];
    const float* H_mid      = (const float*)d_in[1];
    const float* H_last     = (const float*)d_in[2];
    const float* S0         = (const float*)d_in[3];
    const float* S_mid      = (const float*)d_in[4];
    const float* S_last     = (const float*)d_in[5];
    const float* theta0     = (const float*)d_in[6];
    const float* theta_mid  = (const float*)d_in[7];
    const float* theta_last = (const float*)d_in[8];
    const float* precip     = (const float*)d_in[9];
    float* out = (float*)d_out;

    k_layer0<<<97, 128>>>(H0, S0, theta0, precip, out, S_mid, theta_mid);
    for (int l = 0; l < NM; ++l)
        k_mid<<<NB, 128>>>(l, H_mid, S_mid, theta_mid, precip, out);
    k_last<<<4, 256>>>(H_last, S_last, theta_last, precip, out);
}